// round 13
// baseline (speedup 1.0000x reference)
#include <cuda_runtime.h>

#define NC 18
#define CS 4
#define CH 72
#define NP 4096
#define LOG2E 1.44269504088896340736f

typedef unsigned long long ull;

// Scratch (no allocations allowed): __device__ globals (~90 MB).
__device__ float g_qcT[NC][CS][NP];        // chunk q transposed, pre-scaled log2e/64
__device__ float g_kcT[NC][CS][NP];        // chunk k (raw)
__device__ float g_vcT[NC][CS][NP];        // chunk v (raw; 1/Z folded in regs)
__device__ float g_qg[NP][CH];             // global q, pre-scaled log2e/64
__device__ float g_kg[NP][CH];
__device__ float g_vg[NP][CH];             // becomes v/Z after k_rowsum_fold
__device__ float g_E[NP][NP];              // exp2 global scores e[j][i]
__device__ float g_outGPart[8][NP][CH];    // j-segment partials of global output
__device__ float g_Apart[16][NC][34];      // k-moment partials (coeff-folded)
__device__ float g_Bpart[8][NC][CS][35];   // v-weighted q-moment partials

#define L1C 0.6931471805599453f
#define L2C 0.2402265069591007f
#define L3C 0.05550410866482158f
__constant__ float c_coef[34] = {
    L1C, L1C, L1C, L1C,
    L2C, 2*L2C, 2*L2C, 2*L2C, L2C, 2*L2C, 2*L2C, L2C, 2*L2C, L2C,
    L3C, 3*L3C, 3*L3C, 3*L3C, 3*L3C, 6*L3C, 6*L3C, 3*L3C, 6*L3C, 3*L3C,
    L3C, 3*L3C, 3*L3C, 3*L3C, 6*L3C, 3*L3C, L3C, 3*L3C, 3*L3C, L3C};

__device__ __forceinline__ float fexp2(float x) {
    float r; asm("ex2.approx.f32 %0, %1;" : "=f"(r) : "f"(x)); return r;
}
__device__ __forceinline__ ull pfma(ull a, ull b, ull c) {
    ull d; asm("fma.rn.f32x2 %0, %1, %2, %3;" : "=l"(d) : "l"(a), "l"(b), "l"(c)); return d;
}
__device__ __forceinline__ ull padd(ull a, ull b) {
    ull d; asm("add.rn.f32x2 %0, %1, %2;" : "=l"(d) : "l"(a), "l"(b)); return d;
}
__device__ __forceinline__ ull pack2(float lo, float hi) {
    ull d; asm("mov.b64 %0, {%1, %2};" : "=l"(d) : "f"(lo), "f"(hi)); return d;
}
__device__ __forceinline__ float2 unpack2(ull v) {
    float2 f; asm("mov.b64 {%0, %1}, %2;" : "=f"(f.x), "=f"(f.y) : "l"(v)); return f;
}

__device__ __forceinline__ void build_mono(const float q[4], float m[34]) {
#pragma unroll
    for (int c = 0; c < 4; c++) m[c] = q[c];
    int p = 4;
#pragma unroll
    for (int a = 0; a < 4; a++)
#pragma unroll
        for (int b = a; b < 4; b++) m[p++] = q[a] * q[b];
#pragma unroll
    for (int a = 0; a < 4; a++)
#pragma unroll
        for (int b = a; b < 4; b++)
#pragma unroll
            for (int c = b; c < 4; c++) m[p++] = q[a] * q[b] * q[c];
}

// ---------------------------------------------------------------------------
// STAGE 1 (288 threads): blocks [0,288) chunk projections + k-moment partials;
// blocks [288,544) global 72-ch projection with in-block W transpose (dyn smem).
__global__ void k_stage1(const float* __restrict__ x,
                         const float* __restrict__ Wq, const float* __restrict__ bq,
                         const float* __restrict__ Wk, const float* __restrict__ bk,
                         const float* __restrict__ Wv, const float* __restrict__ bv,
                         const float* __restrict__ WqG, const float* __restrict__ bqG,
                         const float* __restrict__ WkG, const float* __restrict__ bkG,
                         const float* __restrict__ WvG, const float* __restrict__ bvG) {
    extern __shared__ float dyn[];
    int bid = blockIdx.x;
    int tid = threadIdx.x;  // 0..287
    if (bid < 288) {
        int bx = bid & 15, n = bid >> 4;
        __shared__ float red[8][34];
        float m[34];
        if (tid < 256) {
            int p = bx * 256 + tid;
            float xv[CS];
#pragma unroll
            for (int c = 0; c < CS; c++) xv[c] = x[(n * CS + c) * NP + p];
            float q[CS], k[CS], v[CS];
#pragma unroll
            for (int o = 0; o < CS; o++) {
                float aq = bq[n * CS + o], ak = bk[n * CS + o], av = bv[n * CS + o];
#pragma unroll
                for (int c = 0; c < CS; c++) {
                    aq += Wq[(n * CS + o) * CS + c] * xv[c];
                    ak += Wk[(n * CS + o) * CS + c] * xv[c];
                    av += Wv[(n * CS + o) * CS + c] * xv[c];
                }
                q[o] = aq * (LOG2E / 64.0f);
                k[o] = ak;
                v[o] = av;
            }
#pragma unroll
            for (int o = 0; o < CS; o++) {
                g_qcT[n][o][p] = q[o];
                g_kcT[n][o][p] = k[o];
                g_vcT[n][o][p] = v[o];
            }
            build_mono(k, m);
#pragma unroll
            for (int pp = 0; pp < 34; pp++)
#pragma unroll
                for (int off = 16; off; off >>= 1)
                    m[pp] += __shfl_down_sync(0xffffffffu, m[pp], off);
            int w = tid >> 5, l = tid & 31;
            if (l == 0)
#pragma unroll
                for (int pp = 0; pp < 34; pp++) red[w][pp] = m[pp];
        }
        __syncthreads();
        if (tid < 34) {
            float s = 0.f;
#pragma unroll
            for (int w2 = 0; w2 < 8; w2++) s += red[w2][tid];
            g_Apart[bx][n][tid] = s * c_coef[tid];
        }
    } else {
        float* wt = dyn;                    // [3][72][72] transposed: wt[m][c][o]
        float* xs = dyn + 3 * CH * CH;      // [72][16]
        const float* Wsrc[3] = {WqG, WkG, WvG};
#pragma unroll
        for (int mm = 0; mm < 3; mm++) {
            const float* Ws = Wsrc[mm];
            for (int r = tid; r < CH * CH; r += 288) {
                int o = r / CH, c = r % CH;
                wt[mm * CH * CH + c * CH + o] = Ws[r];
            }
        }
        int p0 = (bid - 288) * 16;
        {
            int c = tid >> 2, pp4 = (tid & 3) * 4;
            *(float4*)&xs[c * 16 + pp4] = *(const float4*)&x[c * NP + p0 + pp4];
        }
        __syncthreads();
        int o = tid % 72, pg = tid / 72;
        float aq[4], ak[4], av[4];
        float bqv = bqG[o], bkv = bkG[o], bvv = bvG[o];
#pragma unroll
        for (int t = 0; t < 4; t++) { aq[t] = bqv; ak[t] = bkv; av[t] = bvv; }
        for (int c = 0; c < CH; c++) {
            float wq = wt[0 * CH * CH + c * CH + o];
            float wk = wt[1 * CH * CH + c * CH + o];
            float wv = wt[2 * CH * CH + c * CH + o];
            float4 xv4 = *(const float4*)&xs[c * 16 + pg * 4];
            aq[0] += wq * xv4.x; aq[1] += wq * xv4.y; aq[2] += wq * xv4.z; aq[3] += wq * xv4.w;
            ak[0] += wk * xv4.x; ak[1] += wk * xv4.y; ak[2] += wk * xv4.z; ak[3] += wk * xv4.w;
            av[0] += wv * xv4.x; av[1] += wv * xv4.y; av[2] += wv * xv4.z; av[3] += wv * xv4.w;
        }
#pragma unroll
        for (int t = 0; t < 4; t++) {
            int p = p0 + pg * 4 + t;
            g_qg[p][o] = aq[t] * (LOG2E / 64.0f);
            g_kg[p][o] = ak[t];
            g_vg[p][o] = av[t];
        }
    }
}

// ---------------------------------------------------------------------------
// STAGE 2 (256 threads): blocks [0,144) = momVQZ (Z in regs + B partials);
// blocks [144,400) = global scores E[j][i] = exp2(q_j . k_i).
__global__ void k_stage2() {
    int bid = blockIdx.x;
    int tid = threadIdx.x;
    if (bid < 144) {
        int n = bid >> 3, seg = bid & 7;
        __shared__ float As[34];
        __shared__ float red[8][4][35];
        if (tid < 34) {
            float s = 0.f;
#pragma unroll
            for (int sg = 0; sg < 16; sg++) s += g_Apart[sg][n][tid];
            As[tid] = s;
        }
        __syncthreads();
        int c = tid & 3;
        float acc[35];
#pragma unroll
        for (int p = 0; p < 35; p++) acc[p] = 0.f;
        for (int j = seg * 512 + (tid >> 2); j < seg * 512 + 512; j += 64) {
            float q[4];
#pragma unroll
            for (int cc = 0; cc < 4; cc++) q[cc] = g_qcT[n][cc][j];
            float m[34];
            build_mono(q, m);
            float z = (float)NP;
#pragma unroll
            for (int p = 0; p < 34; p++) z += m[p] * As[p];
            float v = g_vcT[n][c][j] * (1.0f / z);
            acc[0] += v;
#pragma unroll
            for (int p = 0; p < 34; p++) acc[1 + p] += v * m[p];
        }
#pragma unroll
        for (int p = 0; p < 35; p++)
#pragma unroll
            for (int off = 16; off >= 4; off >>= 1)
                acc[p] += __shfl_down_sync(0xffffffffu, acc[p], off);
        int w = tid >> 5, l = tid & 31;
        if (l < 4)
#pragma unroll
            for (int p = 0; p < 35; p++) red[w][l][p] = acc[p];
        __syncthreads();
        if (tid < 140) {
            int cc = tid / 35, p = tid % 35;
            float s = 0.f;
#pragma unroll
            for (int w2 = 0; w2 < 8; w2++) s += red[w2][cc][p];
            g_Bpart[seg][n][cc][p] = s;
        }
    } else {
        __shared__ __align__(16) float q_s[64][CH];
        int sb = bid - 144;
        int ib = sb & 15, seg = sb >> 4;
        int i = ib * 256 + tid;
        ull kk2[CH / 2];
        const ulonglong2* krow = (const ulonglong2*)&g_kg[i][0];
#pragma unroll
        for (int c = 0; c < CH / 4; c++) { ulonglong2 t = krow[c]; kk2[2 * c] = t.x; kk2[2 * c + 1] = t.y; }
        for (int jt = 0; jt < 4; jt++) {
            int j0 = seg * 256 + jt * 64;
            const float4* qsrc = (const float4*)&g_qg[j0][0];
            float4* qdst = (float4*)&q_s[0][0];
            for (int r = tid; r < 64 * CH / 4; r += 256) qdst[r] = qsrc[r];
            __syncthreads();
#pragma unroll 2
            for (int j = 0; j < 64; j++) {
                const ulonglong2* qr = (const ulonglong2*)&q_s[j][0];
                ull s0 = 0, s1 = 0, s2 = 0, s3 = 0;
#pragma unroll
                for (int c = 0; c < CH / 4; c += 2) {
                    ulonglong2 t0 = qr[c], t1 = qr[c + 1];
                    s0 = pfma(kk2[2 * c], t0.x, s0);     s1 = pfma(kk2[2 * c + 1], t0.y, s1);
                    s2 = pfma(kk2[2 * c + 2], t1.x, s2); s3 = pfma(kk2[2 * c + 3], t1.y, s3);
                }
                float2 sf = unpack2(padd(padd(s0, s1), padd(s2, s3)));
                g_E[j0 + j][i] = fexp2(sf.x + sf.y);
            }
            __syncthreads();
        }
    }
}

// ---------------------------------------------------------------------------
// Row-sum E -> Z_j, fold 1/Z into vg. Warp per row, 8 rows per block.
__global__ void k_rowsum_fold() {
    int w = threadIdx.x >> 5, l = threadIdx.x & 31;
    int j = blockIdx.x * 8 + w;
    float z = 0.f;
    for (int t = l; t < NP / 4; t += 32) {
        float4 e4 = *(const float4*)&g_E[j][t * 4];
        z += (e4.x + e4.y) + (e4.z + e4.w);
    }
#pragma unroll
    for (int off = 16; off; off >>= 1) z += __shfl_down_sync(0xffffffffu, z, off);
    float rz = __shfl_sync(0xffffffffu, 1.0f / z, 0);
    if (l < CH / 4) {
        float4 v = *(float4*)&g_vg[j][l * 4];
        v.x *= rz; v.y *= rz; v.z *= rz; v.w *= rz;
        *(float4*)&g_vg[j][l * 4] = v;
    }
}

// ---------------------------------------------------------------------------
// Global pass 2, register-blocked: thread = (ch half, i-pair). Per warp-j:
// 9 broadcast LDS.128 + 2 LDG + 36 pfma -> FMA-bound. 8 j-segments of 512.
__global__ void __launch_bounds__(256) k_og2() {
    __shared__ __align__(16) float v_s[64][CH];
    int il = threadIdx.x & 127;
    int ch = threadIdx.x >> 7;           // 0 or 1 -> channels [ch*36, ch*36+36)
    int i0 = blockIdx.x * 256 + il;
    int i1 = i0 + 128;
    int seg = blockIdx.y;                // 0..7 -> j in [seg*512, +512)
    ull outA[18], outB[18];
#pragma unroll
    for (int c = 0; c < 18; c++) { outA[c] = 0; outB[c] = 0; }
    for (int jt = 0; jt < 8; jt++) {
        int j0 = seg * 512 + jt * 64;
        const float4* vsrc = (const float4*)&g_vg[j0][0];
        float4* vdst = (float4*)&v_s[0][0];
        for (int r = threadIdx.x; r < 64 * CH / 4; r += 256) vdst[r] = vsrc[r];
        __syncthreads();
#pragma unroll 2
        for (int j = 0; j < 64; j++) {
            float e0 = __ldg(&g_E[j0 + j][i0]);
            float e1 = __ldg(&g_E[j0 + j][i1]);
            ull ee0 = pack2(e0, e0);
            ull ee1 = pack2(e1, e1);
            const ulonglong2* vr = (const ulonglong2*)&v_s[j][ch * 36];
#pragma unroll
            for (int c = 0; c < 9; c++) {
                ulonglong2 t = vr[c];
                outA[2 * c]     = pfma(t.x, ee0, outA[2 * c]);
                outA[2 * c + 1] = pfma(t.y, ee0, outA[2 * c + 1]);
                outB[2 * c]     = pfma(t.x, ee1, outB[2 * c]);
                outB[2 * c + 1] = pfma(t.y, ee1, outB[2 * c + 1]);
            }
        }
        __syncthreads();
    }
#pragma unroll
    for (int c = 0; c < 9; c++) {
        float2 a = unpack2(outA[2 * c]), b = unpack2(outA[2 * c + 1]);
        *(float4*)&g_outGPart[seg][i0][ch * 36 + c * 4] = make_float4(a.x, a.y, b.x, b.y);
        float2 a2 = unpack2(outB[2 * c]), b2 = unpack2(outB[2 * c + 1]);
        *(float4*)&g_outGPart[seg][i1][ch * 36 + c * 4] = make_float4(a2.x, a2.y, b2.x, b2.y);
    }
}

// ---------------------------------------------------------------------------
// Chunk pass 2 via B-moments + 8 global partials + pooled reduction.
__global__ void k_apply(const float* __restrict__ x, float* __restrict__ out) {
    __shared__ float Bs[4][35];
    int n = blockIdx.y;
    int i = blockIdx.x * 256 + threadIdx.x;
    if (threadIdx.x < 140) {
        int cc = threadIdx.x / 35, p = threadIdx.x % 35;
        float s = 0.f;
#pragma unroll
        for (int sg = 0; sg < 8; sg++) s += g_Bpart[sg][n][cc][p];
        Bs[cc][p] = s;
    }
    __syncthreads();
    float k[4];
#pragma unroll
    for (int c = 0; c < 4; c++) k[c] = g_kcT[n][c][i];
    float m[34];
    build_mono(k, m);
#pragma unroll
    for (int p = 0; p < 34; p++) m[p] *= c_coef[p];
    float a[4];
#pragma unroll
    for (int c = 0; c < 4; c++) {
        float s = Bs[c][0];
#pragma unroll
        for (int p = 0; p < 34; p++) s += m[p] * Bs[c][1 + p];
        a[c] = s;
    }
#pragma unroll
    for (int sg = 0; sg < 8; sg++) {
        float4 og = *(const float4*)&g_outGPart[sg][i][n * 4];
        a[0] += og.x; a[1] += og.y; a[2] += og.z; a[3] += og.w;
    }
    float p = a[0] * x[(n * 4 + 0) * NP + i] + a[1] * x[(n * 4 + 1) * NP + i] +
              a[2] * x[(n * 4 + 2) * NP + i] + a[3] * x[(n * 4 + 3) * NP + i];
    out[n * NP + i] = p;
}

// ---------------------------------------------------------------------------
extern "C" void kernel_launch(void* const* d_in, const int* in_sizes, int n_in,
                              void* d_out, int out_size) {
    const float* x   = (const float*)d_in[0];
    const float* Wq  = (const float*)d_in[1];
    const float* bq  = (const float*)d_in[2];
    const float* Wk  = (const float*)d_in[3];
    const float* bk  = (const float*)d_in[4];
    const float* Wv  = (const float*)d_in[5];
    const float* bv  = (const float*)d_in[6];
    const float* WqG = (const float*)d_in[7];
    const float* bqG = (const float*)d_in[8];
    const float* WkG = (const float*)d_in[9];
    const float* bkG = (const float*)d_in[10];
    const float* WvG = (const float*)d_in[11];
    const float* bvG = (const float*)d_in[12];
    float* out = (float*)d_out;

    const int dynsmem = (3 * CH * CH + CH * 16) * (int)sizeof(float);  // ~66.8 KB
    static int attr_set = 0;
    if (!attr_set) {
        cudaFuncSetAttribute(k_stage1, cudaFuncAttributeMaxDynamicSharedMemorySize, dynsmem);
        attr_set = 1;
    }
    k_stage1<<<544, 288, dynsmem>>>(x, Wq, bq, Wk, bk, Wv, bv,
                                    WqG, bqG, WkG, bkG, WvG, bvG);
    k_stage2<<<400, 256>>>();
    k_rowsum_fold<<<512, 256>>>();
    k_og2<<<dim3(16, 8), 256>>>();
    k_apply<<<dim3(16, 18), 256>>>(x, out);
}

// round 14
// speedup vs baseline: 1.2641x; 1.2641x over previous
#include <cuda_runtime.h>

#define NC 18
#define CS 4
#define CH 72
#define NP 4096
#define LOG2E 1.44269504088896340736f

typedef unsigned long long ull;

// Scratch (no allocations allowed): __device__ globals (~100 MB).
__device__ float g_qcT[NC][CS][NP];        // chunk q transposed, pre-scaled log2e/64
__device__ float g_kcT[NC][CS][NP];        // chunk k (raw)
__device__ float g_vcT[NC][CS][NP];        // chunk v (raw; 1/Z folded in regs)
__device__ float g_qg[NP][CH];             // global q, pre-scaled log2e/64
__device__ float g_kg[NP][CH];
__device__ float g_vg[NP][CH];             // becomes v/Z after k_rowsum_fold
__device__ float g_E[NP][NP];              // exp2 global scores e[j][i]
__device__ float g_outGPart[16][NP][CH];   // j-segment partials of global output
__device__ float g_Apart[16][NC][34];      // k-moment partials (coeff-folded)
__device__ float g_Bpart[8][NC][CS][35];   // v-weighted q-moment partials

#define L1C 0.6931471805599453f
#define L2C 0.2402265069591007f
#define L3C 0.05550410866482158f
__constant__ float c_coef[34] = {
    L1C, L1C, L1C, L1C,
    L2C, 2*L2C, 2*L2C, 2*L2C, L2C, 2*L2C, 2*L2C, L2C, 2*L2C, L2C,
    L3C, 3*L3C, 3*L3C, 3*L3C, 3*L3C, 6*L3C, 6*L3C, 3*L3C, 6*L3C, 3*L3C,
    L3C, 3*L3C, 3*L3C, 3*L3C, 6*L3C, 3*L3C, L3C, 3*L3C, 3*L3C, L3C};

__device__ __forceinline__ float fexp2(float x) {
    float r; asm("ex2.approx.f32 %0, %1;" : "=f"(r) : "f"(x)); return r;
}
__device__ __forceinline__ ull pfma(ull a, ull b, ull c) {
    ull d; asm("fma.rn.f32x2 %0, %1, %2, %3;" : "=l"(d) : "l"(a), "l"(b), "l"(c)); return d;
}
__device__ __forceinline__ ull padd(ull a, ull b) {
    ull d; asm("add.rn.f32x2 %0, %1, %2;" : "=l"(d) : "l"(a), "l"(b)); return d;
}
__device__ __forceinline__ ull pack2(float lo, float hi) {
    ull d; asm("mov.b64 %0, {%1, %2};" : "=l"(d) : "f"(lo), "f"(hi)); return d;
}
__device__ __forceinline__ float2 unpack2(ull v) {
    float2 f; asm("mov.b64 {%0, %1}, %2;" : "=f"(f.x), "=f"(f.y) : "l"(v)); return f;
}

__device__ __forceinline__ void build_mono(const float q[4], float m[34]) {
#pragma unroll
    for (int c = 0; c < 4; c++) m[c] = q[c];
    int p = 4;
#pragma unroll
    for (int a = 0; a < 4; a++)
#pragma unroll
        for (int b = a; b < 4; b++) m[p++] = q[a] * q[b];
#pragma unroll
    for (int a = 0; a < 4; a++)
#pragma unroll
        for (int b = a; b < 4; b++)
#pragma unroll
            for (int c = b; c < 4; c++) m[p++] = q[a] * q[b] * q[c];
}

// ---------------------------------------------------------------------------
// STAGE 1 (288 threads): blocks [0,288) chunk projections + k-moment partials;
// blocks [288,544) global 72-ch projection with in-block W transpose (dyn smem).
__global__ void k_stage1(const float* __restrict__ x,
                         const float* __restrict__ Wq, const float* __restrict__ bq,
                         const float* __restrict__ Wk, const float* __restrict__ bk,
                         const float* __restrict__ Wv, const float* __restrict__ bv,
                         const float* __restrict__ WqG, const float* __restrict__ bqG,
                         const float* __restrict__ WkG, const float* __restrict__ bkG,
                         const float* __restrict__ WvG, const float* __restrict__ bvG) {
    extern __shared__ float dyn[];
    int bid = blockIdx.x;
    int tid = threadIdx.x;  // 0..287
    if (bid < 288) {
        int bx = bid & 15, n = bid >> 4;
        __shared__ float red[8][34];
        float m[34];
        if (tid < 256) {
            int p = bx * 256 + tid;
            float xv[CS];
#pragma unroll
            for (int c = 0; c < CS; c++) xv[c] = x[(n * CS + c) * NP + p];
            float q[CS], k[CS], v[CS];
#pragma unroll
            for (int o = 0; o < CS; o++) {
                float aq = bq[n * CS + o], ak = bk[n * CS + o], av = bv[n * CS + o];
#pragma unroll
                for (int c = 0; c < CS; c++) {
                    aq += Wq[(n * CS + o) * CS + c] * xv[c];
                    ak += Wk[(n * CS + o) * CS + c] * xv[c];
                    av += Wv[(n * CS + o) * CS + c] * xv[c];
                }
                q[o] = aq * (LOG2E / 64.0f);
                k[o] = ak;
                v[o] = av;
            }
#pragma unroll
            for (int o = 0; o < CS; o++) {
                g_qcT[n][o][p] = q[o];
                g_kcT[n][o][p] = k[o];
                g_vcT[n][o][p] = v[o];
            }
            build_mono(k, m);
#pragma unroll
            for (int pp = 0; pp < 34; pp++)
#pragma unroll
                for (int off = 16; off; off >>= 1)
                    m[pp] += __shfl_down_sync(0xffffffffu, m[pp], off);
            int w = tid >> 5, l = tid & 31;
            if (l == 0)
#pragma unroll
                for (int pp = 0; pp < 34; pp++) red[w][pp] = m[pp];
        }
        __syncthreads();
        if (tid < 34) {
            float s = 0.f;
#pragma unroll
            for (int w2 = 0; w2 < 8; w2++) s += red[w2][tid];
            g_Apart[bx][n][tid] = s * c_coef[tid];
        }
    } else {
        float* wt = dyn;                    // [3][72][72] transposed: wt[m][c][o]
        float* xs = dyn + 3 * CH * CH;      // [72][16]
        const float* Wsrc[3] = {WqG, WkG, WvG};
#pragma unroll
        for (int mm = 0; mm < 3; mm++) {
            const float* Ws = Wsrc[mm];
            for (int r = tid; r < CH * CH; r += 288) {
                int o = r / CH, c = r % CH;
                wt[mm * CH * CH + c * CH + o] = Ws[r];
            }
        }
        int p0 = (bid - 288) * 16;
        {
            int c = tid >> 2, pp4 = (tid & 3) * 4;
            *(float4*)&xs[c * 16 + pp4] = *(const float4*)&x[c * NP + p0 + pp4];
        }
        __syncthreads();
        int o = tid % 72, pg = tid / 72;
        float aq[4], ak[4], av[4];
        float bqv = bqG[o], bkv = bkG[o], bvv = bvG[o];
#pragma unroll
        for (int t = 0; t < 4; t++) { aq[t] = bqv; ak[t] = bkv; av[t] = bvv; }
        for (int c = 0; c < CH; c++) {
            float wq = wt[0 * CH * CH + c * CH + o];
            float wk = wt[1 * CH * CH + c * CH + o];
            float wv = wt[2 * CH * CH + c * CH + o];
            float4 xv4 = *(const float4*)&xs[c * 16 + pg * 4];
            aq[0] += wq * xv4.x; aq[1] += wq * xv4.y; aq[2] += wq * xv4.z; aq[3] += wq * xv4.w;
            ak[0] += wk * xv4.x; ak[1] += wk * xv4.y; ak[2] += wk * xv4.z; ak[3] += wk * xv4.w;
            av[0] += wv * xv4.x; av[1] += wv * xv4.y; av[2] += wv * xv4.z; av[3] += wv * xv4.w;
        }
#pragma unroll
        for (int t = 0; t < 4; t++) {
            int p = p0 + pg * 4 + t;
            g_qg[p][o] = aq[t] * (LOG2E / 64.0f);
            g_kg[p][o] = ak[t];
            g_vg[p][o] = av[t];
        }
    }
}

// ---------------------------------------------------------------------------
// STAGE 2 (256 threads): blocks [0,144) = momVQZ (Z in regs + B partials);
// blocks [144,400) = global scores E[j][i] = exp2(q_j . k_i).
__global__ void k_stage2() {
    int bid = blockIdx.x;
    int tid = threadIdx.x;
    if (bid < 144) {
        int n = bid >> 3, seg = bid & 7;
        __shared__ float As[34];
        __shared__ float red[8][4][35];
        if (tid < 34) {
            float s = 0.f;
#pragma unroll
            for (int sg = 0; sg < 16; sg++) s += g_Apart[sg][n][tid];
            As[tid] = s;
        }
        __syncthreads();
        int c = tid & 3;
        float acc[35];
#pragma unroll
        for (int p = 0; p < 35; p++) acc[p] = 0.f;
        for (int j = seg * 512 + (tid >> 2); j < seg * 512 + 512; j += 64) {
            float q[4];
#pragma unroll
            for (int cc = 0; cc < 4; cc++) q[cc] = g_qcT[n][cc][j];
            float m[34];
            build_mono(q, m);
            float z = (float)NP;
#pragma unroll
            for (int p = 0; p < 34; p++) z += m[p] * As[p];
            float v = g_vcT[n][c][j] * (1.0f / z);
            acc[0] += v;
#pragma unroll
            for (int p = 0; p < 34; p++) acc[1 + p] += v * m[p];
        }
#pragma unroll
        for (int p = 0; p < 35; p++)
#pragma unroll
            for (int off = 16; off >= 4; off >>= 1)
                acc[p] += __shfl_down_sync(0xffffffffu, acc[p], off);
        int w = tid >> 5, l = tid & 31;
        if (l < 4)
#pragma unroll
            for (int p = 0; p < 35; p++) red[w][l][p] = acc[p];
        __syncthreads();
        if (tid < 140) {
            int cc = tid / 35, p = tid % 35;
            float s = 0.f;
#pragma unroll
            for (int w2 = 0; w2 < 8; w2++) s += red[w2][cc][p];
            g_Bpart[seg][n][cc][p] = s;
        }
    } else {
        __shared__ __align__(16) float q_s[64][CH];
        int sb = bid - 144;
        int ib = sb & 15, seg = sb >> 4;
        int i = ib * 256 + tid;
        ull kk2[CH / 2];
        const ulonglong2* krow = (const ulonglong2*)&g_kg[i][0];
#pragma unroll
        for (int c = 0; c < CH / 4; c++) { ulonglong2 t = krow[c]; kk2[2 * c] = t.x; kk2[2 * c + 1] = t.y; }
        for (int jt = 0; jt < 4; jt++) {
            int j0 = seg * 256 + jt * 64;
            const float4* qsrc = (const float4*)&g_qg[j0][0];
            float4* qdst = (float4*)&q_s[0][0];
            for (int r = tid; r < 64 * CH / 4; r += 256) qdst[r] = qsrc[r];
            __syncthreads();
#pragma unroll 2
            for (int j = 0; j < 64; j++) {
                const ulonglong2* qr = (const ulonglong2*)&q_s[j][0];
                ull s0 = 0, s1 = 0, s2 = 0, s3 = 0;
#pragma unroll
                for (int c = 0; c < CH / 4; c += 2) {
                    ulonglong2 t0 = qr[c], t1 = qr[c + 1];
                    s0 = pfma(kk2[2 * c], t0.x, s0);     s1 = pfma(kk2[2 * c + 1], t0.y, s1);
                    s2 = pfma(kk2[2 * c + 2], t1.x, s2); s3 = pfma(kk2[2 * c + 3], t1.y, s3);
                }
                float2 sf = unpack2(padd(padd(s0, s1), padd(s2, s3)));
                g_E[j0 + j][i] = fexp2(sf.x + sf.y);
            }
            __syncthreads();
        }
    }
}

// ---------------------------------------------------------------------------
// Row-sum E -> Z_j, fold 1/Z into vg. Warp per row, 8 rows per block.
__global__ void k_rowsum_fold() {
    int w = threadIdx.x >> 5, l = threadIdx.x & 31;
    int j = blockIdx.x * 8 + w;
    float z = 0.f;
    for (int t = l; t < NP / 4; t += 32) {
        float4 e4 = *(const float4*)&g_E[j][t * 4];
        z += (e4.x + e4.y) + (e4.z + e4.w);
    }
#pragma unroll
    for (int off = 16; off; off >>= 1) z += __shfl_down_sync(0xffffffffu, z, off);
    float rz = __shfl_sync(0xffffffffu, 1.0f / z, 0);
    if (l < CH / 4) {
        float4 v = *(float4*)&g_vg[j][l * 4];
        v.x *= rz; v.y *= rz; v.z *= rz; v.w *= rz;
        *(float4*)&g_vg[j][l * 4] = v;
    }
}

// ---------------------------------------------------------------------------
// Global pass 2: R12 inner loop (ch-half x 2 i-cols, 9 LDS + 2 LDG + 36 pfma
// per thread-j) at R11 geometry (128-thr blocks, grid (32,16) = 512 blocks).
__global__ void __launch_bounds__(128) k_og2() {
    __shared__ __align__(16) float v_s[64][CH];
    int lane = threadIdx.x & 63;
    int ch = threadIdx.x >> 6;           // 0/1 -> channels [ch*36, ch*36+36)
    int i0 = blockIdx.x * 128 + lane;
    int i1 = i0 + 64;
    int seg = blockIdx.y;                // 0..15 -> j in [seg*256, +256)
    ull outA[18], outB[18];
#pragma unroll
    for (int c = 0; c < 18; c++) { outA[c] = 0; outB[c] = 0; }
    for (int jt = 0; jt < 4; jt++) {
        int j0 = seg * 256 + jt * 64;
        const float4* vsrc = (const float4*)&g_vg[j0][0];
        float4* vdst = (float4*)&v_s[0][0];
        for (int r = threadIdx.x; r < 64 * CH / 4; r += 128) vdst[r] = vsrc[r];
        __syncthreads();
#pragma unroll 4
        for (int j = 0; j < 64; j++) {
            float e0 = __ldg(&g_E[j0 + j][i0]);
            float e1 = __ldg(&g_E[j0 + j][i1]);
            ull ee0 = pack2(e0, e0);
            ull ee1 = pack2(e1, e1);
            const ulonglong2* vr = (const ulonglong2*)&v_s[j][ch * 36];
#pragma unroll
            for (int c = 0; c < 9; c++) {
                ulonglong2 t = vr[c];
                outA[2 * c]     = pfma(t.x, ee0, outA[2 * c]);
                outA[2 * c + 1] = pfma(t.y, ee0, outA[2 * c + 1]);
                outB[2 * c]     = pfma(t.x, ee1, outB[2 * c]);
                outB[2 * c + 1] = pfma(t.y, ee1, outB[2 * c + 1]);
            }
        }
        __syncthreads();
    }
#pragma unroll
    for (int c = 0; c < 9; c++) {
        float2 a = unpack2(outA[2 * c]), b = unpack2(outA[2 * c + 1]);
        *(float4*)&g_outGPart[seg][i0][ch * 36 + c * 4] = make_float4(a.x, a.y, b.x, b.y);
        float2 a2 = unpack2(outB[2 * c]), b2 = unpack2(outB[2 * c + 1]);
        *(float4*)&g_outGPart[seg][i1][ch * 36 + c * 4] = make_float4(a2.x, a2.y, b2.x, b2.y);
    }
}

// ---------------------------------------------------------------------------
// Chunk pass 2 via B-moments + 16 global partials + pooled reduction.
__global__ void k_apply(const float* __restrict__ x, float* __restrict__ out) {
    __shared__ float Bs[4][35];
    int n = blockIdx.y;
    int i = blockIdx.x * 256 + threadIdx.x;
    if (threadIdx.x < 140) {
        int cc = threadIdx.x / 35, p = threadIdx.x % 35;
        float s = 0.f;
#pragma unroll
        for (int sg = 0; sg < 8; sg++) s += g_Bpart[sg][n][cc][p];
        Bs[cc][p] = s;
    }
    __syncthreads();
    float k[4];
#pragma unroll
    for (int c = 0; c < 4; c++) k[c] = g_kcT[n][c][i];
    float m[34];
    build_mono(k, m);
#pragma unroll
    for (int p = 0; p < 34; p++) m[p] *= c_coef[p];
    float a[4];
#pragma unroll
    for (int c = 0; c < 4; c++) {
        float s = Bs[c][0];
#pragma unroll
        for (int p = 0; p < 34; p++) s += m[p] * Bs[c][1 + p];
        a[c] = s;
    }
#pragma unroll
    for (int sg = 0; sg < 16; sg++) {
        float4 og = *(const float4*)&g_outGPart[sg][i][n * 4];
        a[0] += og.x; a[1] += og.y; a[2] += og.z; a[3] += og.w;
    }
    float p = a[0] * x[(n * 4 + 0) * NP + i] + a[1] * x[(n * 4 + 1) * NP + i] +
              a[2] * x[(n * 4 + 2) * NP + i] + a[3] * x[(n * 4 + 3) * NP + i];
    out[n * NP + i] = p;
}

// ---------------------------------------------------------------------------
extern "C" void kernel_launch(void* const* d_in, const int* in_sizes, int n_in,
                              void* d_out, int out_size) {
    const float* x   = (const float*)d_in[0];
    const float* Wq  = (const float*)d_in[1];
    const float* bq  = (const float*)d_in[2];
    const float* Wk  = (const float*)d_in[3];
    const float* bk  = (const float*)d_in[4];
    const float* Wv  = (const float*)d_in[5];
    const float* bv  = (const float*)d_in[6];
    const float* WqG = (const float*)d_in[7];
    const float* bqG = (const float*)d_in[8];
    const float* WkG = (const float*)d_in[9];
    const float* bkG = (const float*)d_in[10];
    const float* WvG = (const float*)d_in[11];
    const float* bvG = (const float*)d_in[12];
    float* out = (float*)d_out;

    const int dynsmem = (3 * CH * CH + CH * 16) * (int)sizeof(float);  // ~66.8 KB
    static int attr_set = 0;
    if (!attr_set) {
        cudaFuncSetAttribute(k_stage1, cudaFuncAttributeMaxDynamicSharedMemorySize, dynsmem);
        attr_set = 1;
    }
    k_stage1<<<544, 288, dynsmem>>>(x, Wq, bq, Wk, bk, Wv, bv,
                                    WqG, bqG, WkG, bkG, WvG, bvG);
    k_stage2<<<400, 256>>>();
    k_rowsum_fold<<<512, 256>>>();
    k_og2<<<dim3(32, 16), 128>>>();
    k_apply<<<dim3(16, 18), 256>>>(x, out);
}

// round 15
// speedup vs baseline: 1.3011x; 1.0293x over previous
#include <cuda_runtime.h>

#define NC 18
#define CS 4
#define CH 72
#define NP 4096
#define LOG2E 1.44269504088896340736f

typedef unsigned long long ull;

// Scratch (no allocations allowed): __device__ globals (~100 MB).
__device__ float g_qcT[NC][CS][NP];        // chunk q transposed, pre-scaled log2e/64
__device__ float g_kcT[NC][CS][NP];        // chunk k (raw)
__device__ float g_vcT[NC][CS][NP];        // chunk v (raw; 1/Z folded in regs)
__device__ float g_qg[NP][CH];             // global q, pre-scaled log2e/64
__device__ float g_kg[NP][CH];
__device__ float g_vg[NP][CH];             // becomes v/Z after k_rowsum_fold
__device__ float g_E[NP][NP];              // exp2 global scores e[j][i]
__device__ float g_outGPart[16][NP][CH];   // j-segment partials of global output
__device__ float g_Apart[16][NC][34];      // k-moment partials (coeff-folded)
__device__ float g_Bpart[8][NC][CS][35];   // v-weighted q-moment partials

#define L1C 0.6931471805599453f
#define L2C 0.2402265069591007f
#define L3C 0.05550410866482158f
__constant__ float c_coef[34] = {
    L1C, L1C, L1C, L1C,
    L2C, 2*L2C, 2*L2C, 2*L2C, L2C, 2*L2C, 2*L2C, L2C, 2*L2C, L2C,
    L3C, 3*L3C, 3*L3C, 3*L3C, 3*L3C, 6*L3C, 6*L3C, 3*L3C, 6*L3C, 3*L3C,
    L3C, 3*L3C, 3*L3C, 3*L3C, 6*L3C, 3*L3C, L3C, 3*L3C, 3*L3C, L3C};

__device__ __forceinline__ float fexp2(float x) {
    float r; asm("ex2.approx.f32 %0, %1;" : "=f"(r) : "f"(x)); return r;
}
__device__ __forceinline__ ull pfma(ull a, ull b, ull c) {
    ull d; asm("fma.rn.f32x2 %0, %1, %2, %3;" : "=l"(d) : "l"(a), "l"(b), "l"(c)); return d;
}
__device__ __forceinline__ ull padd(ull a, ull b) {
    ull d; asm("add.rn.f32x2 %0, %1, %2;" : "=l"(d) : "l"(a), "l"(b)); return d;
}
__device__ __forceinline__ ull pack2(float lo, float hi) {
    ull d; asm("mov.b64 %0, {%1, %2};" : "=l"(d) : "f"(lo), "f"(hi)); return d;
}
__device__ __forceinline__ float2 unpack2(ull v) {
    float2 f; asm("mov.b64 {%0, %1}, %2;" : "=f"(f.x), "=f"(f.y) : "l"(v)); return f;
}

__device__ __forceinline__ void build_mono(const float q[4], float m[34]) {
#pragma unroll
    for (int c = 0; c < 4; c++) m[c] = q[c];
    int p = 4;
#pragma unroll
    for (int a = 0; a < 4; a++)
#pragma unroll
        for (int b = a; b < 4; b++) m[p++] = q[a] * q[b];
#pragma unroll
    for (int a = 0; a < 4; a++)
#pragma unroll
        for (int b = a; b < 4; b++)
#pragma unroll
            for (int c = b; c < 4; c++) m[p++] = q[a] * q[b] * q[c];
}

// ---------------------------------------------------------------------------
// STAGE 1 (288 threads): blocks [0,288) chunk projections + k-moment partials;
// blocks [288,544) global 72-ch projection with in-block W transpose (dyn smem).
__global__ void k_stage1(const float* __restrict__ x,
                         const float* __restrict__ Wq, const float* __restrict__ bq,
                         const float* __restrict__ Wk, const float* __restrict__ bk,
                         const float* __restrict__ Wv, const float* __restrict__ bv,
                         const float* __restrict__ WqG, const float* __restrict__ bqG,
                         const float* __restrict__ WkG, const float* __restrict__ bkG,
                         const float* __restrict__ WvG, const float* __restrict__ bvG) {
    extern __shared__ float dyn[];
    int bid = blockIdx.x;
    int tid = threadIdx.x;  // 0..287
    if (bid < 288) {
        int bx = bid & 15, n = bid >> 4;
        __shared__ float red[8][34];
        float m[34];
        if (tid < 256) {
            int p = bx * 256 + tid;
            float xv[CS];
#pragma unroll
            for (int c = 0; c < CS; c++) xv[c] = x[(n * CS + c) * NP + p];
            float q[CS], k[CS], v[CS];
#pragma unroll
            for (int o = 0; o < CS; o++) {
                float aq = bq[n * CS + o], ak = bk[n * CS + o], av = bv[n * CS + o];
#pragma unroll
                for (int c = 0; c < CS; c++) {
                    aq += Wq[(n * CS + o) * CS + c] * xv[c];
                    ak += Wk[(n * CS + o) * CS + c] * xv[c];
                    av += Wv[(n * CS + o) * CS + c] * xv[c];
                }
                q[o] = aq * (LOG2E / 64.0f);
                k[o] = ak;
                v[o] = av;
            }
#pragma unroll
            for (int o = 0; o < CS; o++) {
                g_qcT[n][o][p] = q[o];
                g_kcT[n][o][p] = k[o];
                g_vcT[n][o][p] = v[o];
            }
            build_mono(k, m);
#pragma unroll
            for (int pp = 0; pp < 34; pp++)
#pragma unroll
                for (int off = 16; off; off >>= 1)
                    m[pp] += __shfl_down_sync(0xffffffffu, m[pp], off);
            int w = tid >> 5, l = tid & 31;
            if (l == 0)
#pragma unroll
                for (int pp = 0; pp < 34; pp++) red[w][pp] = m[pp];
        }
        __syncthreads();
        if (tid < 34) {
            float s = 0.f;
#pragma unroll
            for (int w2 = 0; w2 < 8; w2++) s += red[w2][tid];
            g_Apart[bx][n][tid] = s * c_coef[tid];
        }
    } else {
        float* wt = dyn;                    // [3][72][72] transposed: wt[m][c][o]
        float* xs = dyn + 3 * CH * CH;      // [72][16]
        const float* Wsrc[3] = {WqG, WkG, WvG};
#pragma unroll
        for (int mm = 0; mm < 3; mm++) {
            const float* Ws = Wsrc[mm];
            for (int r = tid; r < CH * CH; r += 288) {
                int o = r / CH, c = r % CH;
                wt[mm * CH * CH + c * CH + o] = Ws[r];
            }
        }
        int p0 = (bid - 288) * 16;
        {
            int c = tid >> 2, pp4 = (tid & 3) * 4;
            *(float4*)&xs[c * 16 + pp4] = *(const float4*)&x[c * NP + p0 + pp4];
        }
        __syncthreads();
        int o = tid % 72, pg = tid / 72;
        float aq[4], ak[4], av[4];
        float bqv = bqG[o], bkv = bkG[o], bvv = bvG[o];
#pragma unroll
        for (int t = 0; t < 4; t++) { aq[t] = bqv; ak[t] = bkv; av[t] = bvv; }
        for (int c = 0; c < CH; c++) {
            float wq = wt[0 * CH * CH + c * CH + o];
            float wk = wt[1 * CH * CH + c * CH + o];
            float wv = wt[2 * CH * CH + c * CH + o];
            float4 xv4 = *(const float4*)&xs[c * 16 + pg * 4];
            aq[0] += wq * xv4.x; aq[1] += wq * xv4.y; aq[2] += wq * xv4.z; aq[3] += wq * xv4.w;
            ak[0] += wk * xv4.x; ak[1] += wk * xv4.y; ak[2] += wk * xv4.z; ak[3] += wk * xv4.w;
            av[0] += wv * xv4.x; av[1] += wv * xv4.y; av[2] += wv * xv4.z; av[3] += wv * xv4.w;
        }
#pragma unroll
        for (int t = 0; t < 4; t++) {
            int p = p0 + pg * 4 + t;
            g_qg[p][o] = aq[t] * (LOG2E / 64.0f);
            g_kg[p][o] = ak[t];
            g_vg[p][o] = av[t];
        }
    }
}

// ---------------------------------------------------------------------------
// STAGE 2 (256 threads): blocks [0,144) = momVQZ (Z in regs + B partials);
// blocks [144,400) = global scores E[j][i] = exp2(q_j . k_i).
__global__ void k_stage2() {
    int bid = blockIdx.x;
    int tid = threadIdx.x;
    if (bid < 144) {
        int n = bid >> 3, seg = bid & 7;
        __shared__ float As[34];
        __shared__ float red[8][4][35];
        if (tid < 34) {
            float s = 0.f;
#pragma unroll
            for (int sg = 0; sg < 16; sg++) s += g_Apart[sg][n][tid];
            As[tid] = s;
        }
        __syncthreads();
        int c = tid & 3;
        float acc[35];
#pragma unroll
        for (int p = 0; p < 35; p++) acc[p] = 0.f;
        for (int j = seg * 512 + (tid >> 2); j < seg * 512 + 512; j += 64) {
            float q[4];
#pragma unroll
            for (int cc = 0; cc < 4; cc++) q[cc] = g_qcT[n][cc][j];
            float m[34];
            build_mono(q, m);
            float z = (float)NP;
#pragma unroll
            for (int p = 0; p < 34; p++) z += m[p] * As[p];
            float v = g_vcT[n][c][j] * (1.0f / z);
            acc[0] += v;
#pragma unroll
            for (int p = 0; p < 34; p++) acc[1 + p] += v * m[p];
        }
#pragma unroll
        for (int p = 0; p < 35; p++)
#pragma unroll
            for (int off = 16; off >= 4; off >>= 1)
                acc[p] += __shfl_down_sync(0xffffffffu, acc[p], off);
        int w = tid >> 5, l = tid & 31;
        if (l < 4)
#pragma unroll
            for (int p = 0; p < 35; p++) red[w][l][p] = acc[p];
        __syncthreads();
        if (tid < 140) {
            int cc = tid / 35, p = tid % 35;
            float s = 0.f;
#pragma unroll
            for (int w2 = 0; w2 < 8; w2++) s += red[w2][cc][p];
            g_Bpart[seg][n][cc][p] = s;
        }
    } else {
        __shared__ __align__(16) float q_s[64][CH];
        int sb = bid - 144;
        int ib = sb & 15, seg = sb >> 4;
        int i = ib * 256 + tid;
        ull kk2[CH / 2];
        const ulonglong2* krow = (const ulonglong2*)&g_kg[i][0];
#pragma unroll
        for (int c = 0; c < CH / 4; c++) { ulonglong2 t = krow[c]; kk2[2 * c] = t.x; kk2[2 * c + 1] = t.y; }
        for (int jt = 0; jt < 4; jt++) {
            int j0 = seg * 256 + jt * 64;
            const float4* qsrc = (const float4*)&g_qg[j0][0];
            float4* qdst = (float4*)&q_s[0][0];
            for (int r = tid; r < 64 * CH / 4; r += 256) qdst[r] = qsrc[r];
            __syncthreads();
#pragma unroll 2
            for (int j = 0; j < 64; j++) {
                const ulonglong2* qr = (const ulonglong2*)&q_s[j][0];
                ull s0 = 0, s1 = 0, s2 = 0, s3 = 0;
#pragma unroll
                for (int c = 0; c < CH / 4; c += 2) {
                    ulonglong2 t0 = qr[c], t1 = qr[c + 1];
                    s0 = pfma(kk2[2 * c], t0.x, s0);     s1 = pfma(kk2[2 * c + 1], t0.y, s1);
                    s2 = pfma(kk2[2 * c + 2], t1.x, s2); s3 = pfma(kk2[2 * c + 3], t1.y, s3);
                }
                float2 sf = unpack2(padd(padd(s0, s1), padd(s2, s3)));
                g_E[j0 + j][i] = fexp2(sf.x + sf.y);
            }
            __syncthreads();
        }
    }
}

// ---------------------------------------------------------------------------
// Row-sum E -> Z_j, fold 1/Z into vg. Warp per row, 8 rows per block.
__global__ void k_rowsum_fold() {
    int w = threadIdx.x >> 5, l = threadIdx.x & 31;
    int j = blockIdx.x * 8 + w;
    float z = 0.f;
    for (int t = l; t < NP / 4; t += 32) {
        float4 e4 = *(const float4*)&g_E[j][t * 4];
        z += (e4.x + e4.y) + (e4.z + e4.w);
    }
#pragma unroll
    for (int off = 16; off; off >>= 1) z += __shfl_down_sync(0xffffffffu, z, off);
    float rz = __shfl_sync(0xffffffffu, 1.0f / z, 0);
    if (l < CH / 4) {
        float4 v = *(float4*)&g_vg[j][l * 4];
        v.x *= rz; v.y *= rz; v.z *= rz; v.w *= rz;
        *(float4*)&g_vg[j][l * 4] = v;
    }
}

// ---------------------------------------------------------------------------
// Global pass 2: register-blocked (ch-half x 2 i-cols) with E tiles STAGED
// THROUGH SMEM (coalesced cooperative loads; inner loop = short-scoreboard
// LDS only). Per thread-j: 2 LDS.32 (e) + 9 LDS.128 (v bcast) + 36 pfma.
__global__ void __launch_bounds__(128) k_og2() {
    __shared__ __align__(16) float v_s[64][CH];
    __shared__ __align__(16) float e_s[32][128];
    int lane = threadIdx.x & 63;
    int ch = threadIdx.x >> 6;           // 0/1 -> channels [ch*36, ch*36+36)
    int ibase = blockIdx.x * 128;
    int i0 = ibase + lane;
    int i1 = i0 + 64;
    int seg = blockIdx.y;                // 0..15 -> j in [seg*256, +256)
    ull outA[18], outB[18];
#pragma unroll
    for (int c = 0; c < 18; c++) { outA[c] = 0; outB[c] = 0; }
    for (int jt = 0; jt < 4; jt++) {
        int j0 = seg * 256 + jt * 64;
        // v tile for 64 j's (reload every other e-tile; cheap)
        const float4* vsrc = (const float4*)&g_vg[j0][0];
        float4* vdst = (float4*)&v_s[0][0];
        for (int r = threadIdx.x; r < 64 * CH / 4; r += 128) vdst[r] = vsrc[r];
        for (int half = 0; half < 2; half++) {
            int jh = j0 + half * 32;
            // cooperative E tile load: 32 j x 128 i, coalesced, MLP=8
            __syncthreads();
#pragma unroll
            for (int r = 0; r < 8; r++) {
                int idx = r * 128 + threadIdx.x;      // 0..1023 float4 slots
                int row = idx >> 5, col = idx & 31;
                *(float4*)&e_s[row][col * 4] = *(const float4*)&g_E[jh + row][ibase + col * 4];
            }
            __syncthreads();
#pragma unroll 4
            for (int j = 0; j < 32; j++) {
                float e0 = e_s[j][lane];
                float e1 = e_s[j][lane + 64];
                ull ee0 = pack2(e0, e0);
                ull ee1 = pack2(e1, e1);
                const ulonglong2* vr = (const ulonglong2*)&v_s[half * 32 + j][ch * 36];
#pragma unroll
                for (int c = 0; c < 9; c++) {
                    ulonglong2 t = vr[c];
                    outA[2 * c]     = pfma(t.x, ee0, outA[2 * c]);
                    outA[2 * c + 1] = pfma(t.y, ee0, outA[2 * c + 1]);
                    outB[2 * c]     = pfma(t.x, ee1, outB[2 * c]);
                    outB[2 * c + 1] = pfma(t.y, ee1, outB[2 * c + 1]);
                }
            }
        }
        __syncthreads();
    }
#pragma unroll
    for (int c = 0; c < 9; c++) {
        float2 a = unpack2(outA[2 * c]), b = unpack2(outA[2 * c + 1]);
        *(float4*)&g_outGPart[seg][i0][ch * 36 + c * 4] = make_float4(a.x, a.y, b.x, b.y);
        float2 a2 = unpack2(outB[2 * c]), b2 = unpack2(outB[2 * c + 1]);
        *(float4*)&g_outGPart[seg][i1][ch * 36 + c * 4] = make_float4(a2.x, a2.y, b2.x, b2.y);
    }
}

// ---------------------------------------------------------------------------
// Chunk pass 2 via B-moments + 16 global partials + pooled reduction.
__global__ void k_apply(const float* __restrict__ x, float* __restrict__ out) {
    __shared__ float Bs[4][35];
    int n = blockIdx.y;
    int i = blockIdx.x * 256 + threadIdx.x;
    if (threadIdx.x < 140) {
        int cc = threadIdx.x / 35, p = threadIdx.x % 35;
        float s = 0.f;
#pragma unroll
        for (int sg = 0; sg < 8; sg++) s += g_Bpart[sg][n][cc][p];
        Bs[cc][p] = s;
    }
    __syncthreads();
    float k[4];
#pragma unroll
    for (int c = 0; c < 4; c++) k[c] = g_kcT[n][c][i];
    float m[34];
    build_mono(k, m);
#pragma unroll
    for (int p = 0; p < 34; p++) m[p] *= c_coef[p];
    float a[4];
#pragma unroll
    for (int c = 0; c < 4; c++) {
        float s = Bs[c][0];
#pragma unroll
        for (int p = 0; p < 34; p++) s += m[p] * Bs[c][1 + p];
        a[c] = s;
    }
#pragma unroll
    for (int sg = 0; sg < 16; sg++) {
        float4 og = *(const float4*)&g_outGPart[sg][i][n * 4];
        a[0] += og.x; a[1] += og.y; a[2] += og.z; a[3] += og.w;
    }
    float p = a[0] * x[(n * 4 + 0) * NP + i] + a[1] * x[(n * 4 + 1) * NP + i] +
              a[2] * x[(n * 4 + 2) * NP + i] + a[3] * x[(n * 4 + 3) * NP + i];
    out[n * NP + i] = p;
}

// ---------------------------------------------------------------------------
extern "C" void kernel_launch(void* const* d_in, const int* in_sizes, int n_in,
                              void* d_out, int out_size) {
    const float* x   = (const float*)d_in[0];
    const float* Wq  = (const float*)d_in[1];
    const float* bq  = (const float*)d_in[2];
    const float* Wk  = (const float*)d_in[3];
    const float* bk  = (const float*)d_in[4];
    const float* Wv  = (const float*)d_in[5];
    const float* bv  = (const float*)d_in[6];
    const float* WqG = (const float*)d_in[7];
    const float* bqG = (const float*)d_in[8];
    const float* WkG = (const float*)d_in[9];
    const float* bkG = (const float*)d_in[10];
    const float* WvG = (const float*)d_in[11];
    const float* bvG = (const float*)d_in[12];
    float* out = (float*)d_out;

    const int dynsmem = (3 * CH * CH + CH * 16) * (int)sizeof(float);  // ~66.8 KB
    static int attr_set = 0;
    if (!attr_set) {
        cudaFuncSetAttribute(k_stage1, cudaFuncAttributeMaxDynamicSharedMemorySize, dynsmem);
        attr_set = 1;
    }
    k_stage1<<<544, 288, dynsmem>>>(x, Wq, bq, Wk, bk, Wv, bv,
                                    WqG, bqG, WkG, bkG, WvG, bvG);
    k_stage2<<<400, 256>>>();
    k_rowsum_fold<<<512, 256>>>();
    k_og2<<<dim3(32, 16), 128>>>();
    k_apply<<<dim3(16, 18), 256>>>(x, out);
}